// round 7
// baseline (speedup 1.0000x reference)
#include <cuda_runtime.h>
#include <cuda_fp16.h>
#include <math.h>

#define N_NODES  50000
#define D_FEAT   128
#define N_EDGES  600000
#define MAXNORM  (1.0f - 4e-3f)   // (1 - eps)/sqrt(c), c = 1
#define CAP      128              // bucket capacity per row (max degree ~35)
#define CAP_SH   7

// ---------------------------------------------------------------------------
// Scratch (__device__ globals; allocation-free rule).
// g_deg is zero at module load; the gather kernel re-zeroes it at the end of
// every call, so each (captured/replayed) call sees zeros.
// ---------------------------------------------------------------------------
__device__ __half g_tangent[(size_t)N_NODES * D_FEAT]; // fp16 tangent (x*scale)
__device__ int    g_deg[N_NODES];                      // per-row edge count
__device__ int2   g_bucket[(size_t)N_NODES * CAP];     // {col, f32bits(w)}

// ---------------------------------------------------------------------------
// K1 (fused): block-range split.
//   blocks [0, blocksA):       scale  — warp per node, tangent = fp16(x*logmap)
//   blocks [blocksA, gridDim): fill   — thread per edge, scan-free buckets
// The two halves touch disjoint data and run concurrently across SMs.
// ---------------------------------------------------------------------------
__global__ void prep_kernel(const float* __restrict__ x,
                            const int*   __restrict__ erow,
                            const int*   __restrict__ ecol,
                            const float* __restrict__ ew,
                            int n_nodes, int n_edges, int blocksA) {
    if ((int)blockIdx.x < blocksA) {
        // ---- scale half: one warp per node ----
        int gtid = blockIdx.x * blockDim.x + threadIdx.x;
        int warp = gtid >> 5;
        int lane = gtid & 31;
        if (warp >= n_nodes) return;

        float4 v = reinterpret_cast<const float4*>(x)[(size_t)warp * (D_FEAT / 4) + lane];
        float ss = v.x * v.x + v.y * v.y + v.z * v.z + v.w * v.w;
        #pragma unroll
        for (int o = 16; o; o >>= 1) ss += __shfl_xor_sync(0xffffffffu, ss, o);

        float n   = sqrtf(ss);
        float nm  = fmaxf(n, 1e-15f);
        float t   = fminf(nm, 1.0f - 1e-7f);
        float art = 0.5f * (log1pf(t) - log1pf(-t));
        float s   = art / nm;

        half2 h0 = __floats2half2_rn(v.x * s, v.y * s);
        half2 h1 = __floats2half2_rn(v.z * s, v.w * s);
        uint2 pk;
        pk.x = *reinterpret_cast<unsigned*>(&h0);
        pk.y = *reinterpret_cast<unsigned*>(&h1);
        reinterpret_cast<uint2*>(g_tangent)[(size_t)warp * (D_FEAT / 4) + lane] = pk;
    } else {
        // ---- fill half: one thread per edge ----
        int e = (blockIdx.x - blocksA) * blockDim.x + threadIdx.x;
        if (e >= n_edges) return;
        int   r = erow[e];
        int   c = ecol[e];
        float w = ew[e];
        int pos = atomicAdd(&g_deg[r], 1);
        if (pos < CAP) {
            int2 pk; pk.x = c; pk.y = __float_as_int(w);
            g_bucket[((size_t)r << CAP_SH) + pos] = pk;
        }
    }
}

// ---------------------------------------------------------------------------
// K2: warp-per-row fp16 gather + fp32 accumulate + fused expmap0 + proj.
//     Edge metadata via uniform predicated LDG (L1 broadcast, no shfl),
//     unroll-8 so 8 independent tangent gathers are in flight (MLP=8).
//     Lane 0 resets g_deg[row] for the next call (graph replay safety).
// ---------------------------------------------------------------------------
__global__ void gather_kernel(float* __restrict__ out, int n_nodes) {
    int gtid = blockIdx.x * blockDim.x + threadIdx.x;
    int warp = gtid >> 5;
    int lane = gtid & 31;
    if (warp >= n_nodes) return;

    int deg = g_deg[warp];
    if (lane == 0) g_deg[warp] = 0;        // reset for next launch/replay
    deg = min(deg, CAP);

    const int2*  bk = g_bucket + ((size_t)warp << CAP_SH);
    const uint2* tb = reinterpret_cast<const uint2*>(g_tangent);

    float4 acc = make_float4(0.f, 0.f, 0.f, 0.f);

    #pragma unroll 1
    for (int j = 0; j < deg; j += 8) {
        #pragma unroll
        for (int u = 0; u < 8; u++) {
            int  jj = j + u;
            int2 e  = (jj < deg) ? bk[jj] : make_int2(0, 0);   // uniform ld, w=0 pad
            float ww = __int_as_float(e.y);
            uint2 hv = tb[(size_t)e.x * (D_FEAT / 4) + lane];
            float2 f0 = __half22float2(*reinterpret_cast<half2*>(&hv.x));
            float2 f1 = __half22float2(*reinterpret_cast<half2*>(&hv.y));
            acc.x = fmaf(ww, f0.x, acc.x);
            acc.y = fmaf(ww, f0.y, acc.y);
            acc.z = fmaf(ww, f1.x, acc.z);
            acc.w = fmaf(ww, f1.y, acc.w);
        }
    }

    // fused expmap0 + proj: un = max(||u||,1e-15); t = tanh(un);
    //                       f = min(t, MAXNORM) / un
    float ss = acc.x * acc.x + acc.y * acc.y + acc.z * acc.z + acc.w * acc.w;
    #pragma unroll
    for (int o = 16; o; o >>= 1) ss += __shfl_xor_sync(0xffffffffu, ss, o);

    float n  = sqrtf(ss);
    float un = fmaxf(n, 1e-15f);
    float t  = tanhf(un);
    float f  = (t > MAXNORM ? MAXNORM : t) / un;

    acc.x *= f; acc.y *= f; acc.z *= f; acc.w *= f;
    reinterpret_cast<float4*>(out)[(size_t)warp * (D_FEAT / 4) + lane] = acc;
}

// ---------------------------------------------------------------------------
// Launch
// ---------------------------------------------------------------------------
extern "C" void kernel_launch(void* const* d_in, const int* in_sizes, int n_in,
                              void* d_out, int out_size) {
    const float* x    = (const float*)d_in[0];
    const int*   erow = (const int*)d_in[1];
    const int*   ecol = (const int*)d_in[2];
    const float* ew   = (const float*)d_in[3];
    float*       out  = (float*)d_out;

    int n_nodes = in_sizes[0] / D_FEAT;
    int n_edges = in_sizes[3];

    const int T = 256;
    int blocksA = (n_nodes * 32 + T - 1) / T;   // scale: warp per node
    int blocksB = (n_edges + T - 1) / T;        // fill: thread per edge

    prep_kernel<<<blocksA + blocksB, T>>>(x, erow, ecol, ew, n_nodes, n_edges, blocksA);
    gather_kernel<<<blocksA, T>>>(out, n_nodes);
}

// round 9
// speedup vs baseline: 1.4844x; 1.4844x over previous
#include <cuda_runtime.h>
#include <cuda_fp16.h>
#include <math.h>

#define N_NODES  50000
#define D_FEAT   128
#define N_EDGES  600000
#define MAXNORM  (1.0f - 4e-3f)   // (1 - eps)/sqrt(c), c = 1
#define CAP      128              // bucket capacity per row (max degree ~35)
#define CAP_SH   7

// ---------------------------------------------------------------------------
// Scratch (__device__ globals; allocation-free rule).
// g_deg is zero at module load; gather re-zeroes it every call (replay-safe).
// ---------------------------------------------------------------------------
__device__ __half g_tangent[(size_t)N_NODES * D_FEAT]; // fp16 tangent (x*scale)
__device__ int    g_deg[N_NODES];                      // per-row edge count
__device__ int2   g_bucket[(size_t)N_NODES * CAP];     // {col, f32bits(w)}

// ---------------------------------------------------------------------------
// K1 (fused prep): block-range split (measured ~11 us).
//   blocks [0, blocksA):       scale  — warp per node, tangent = fp16(x*logmap)
//   blocks [blocksA, gridDim): fill   — thread per edge, scan-free buckets
// ---------------------------------------------------------------------------
__global__ void prep_kernel(const float* __restrict__ x,
                            const int*   __restrict__ erow,
                            const int*   __restrict__ ecol,
                            const float* __restrict__ ew,
                            int n_nodes, int n_edges, int blocksA) {
    if ((int)blockIdx.x < blocksA) {
        int gtid = blockIdx.x * blockDim.x + threadIdx.x;
        int warp = gtid >> 5;
        int lane = gtid & 31;
        if (warp >= n_nodes) return;

        float4 v = reinterpret_cast<const float4*>(x)[(size_t)warp * (D_FEAT / 4) + lane];
        float ss = v.x * v.x + v.y * v.y + v.z * v.z + v.w * v.w;
        #pragma unroll
        for (int o = 16; o; o >>= 1) ss += __shfl_xor_sync(0xffffffffu, ss, o);

        float n   = sqrtf(ss);
        float nm  = fmaxf(n, 1e-15f);
        float t   = fminf(nm, 1.0f - 1e-7f);
        float art = 0.5f * (log1pf(t) - log1pf(-t));
        float s   = art / nm;

        half2 h0 = __floats2half2_rn(v.x * s, v.y * s);
        half2 h1 = __floats2half2_rn(v.z * s, v.w * s);
        uint2 pk;
        pk.x = *reinterpret_cast<unsigned*>(&h0);
        pk.y = *reinterpret_cast<unsigned*>(&h1);
        reinterpret_cast<uint2*>(g_tangent)[(size_t)warp * (D_FEAT / 4) + lane] = pk;
    } else {
        int e = (blockIdx.x - blocksA) * blockDim.x + threadIdx.x;
        if (e >= n_edges) return;
        int   r = erow[e];
        int   c = ecol[e];
        float w = ew[e];
        int pos = atomicAdd(&g_deg[r], 1);
        if (pos < CAP) {
            int2 pk; pk.x = c; pk.y = __float_as_int(w);
            g_bucket[((size_t)r << CAP_SH) + pos] = pk;
        }
    }
}

// ---------------------------------------------------------------------------
// K2: HALF-WARP (16-lane) per row. Each lane owns 8 feature columns
//     (uint4 = 8 halfs = 16B; 16 lanes cover the 256B fp16 row coalesced).
//     Two independent row chains per warp -> 8 outstanding gathers at
//     unroll-4. All shfls use the OWN half-warp's membermask (the two halves
//     have different trip counts and diverge; full-mask shfl would be UB).
// ---------------------------------------------------------------------------
__global__ void gather_kernel(float* __restrict__ out, int n_nodes) {
    int gtid = blockIdx.x * blockDim.x + threadIdx.x;
    int row  = gtid >> 4;                   // 16-lane group id = node row
    int sl   = gtid & 15;
    unsigned hmask = 0xFFFFu << (threadIdx.x & 16);  // this half-warp's lanes
    if (row >= n_nodes) return;

    int deg = g_deg[row];
    if (sl == 0) g_deg[row] = 0;            // reset for next launch/replay
    deg = min(deg, CAP);

    const int2*  bk = g_bucket + ((size_t)row << CAP_SH);
    const uint4* tb = reinterpret_cast<const uint4*>(g_tangent); // 16B/lane

    float acc[8];
    #pragma unroll
    for (int k = 0; k < 8; k++) acc[k] = 0.f;

    #pragma unroll 1
    for (int j0 = 0; j0 < deg; j0 += 16) {
        int jk = min(16, deg - j0);
        int2 e = (sl < jk) ? bk[j0 + sl] : make_int2(0, 0);   // w=0 pad
        int kk = (jk + 3) & ~3;
        #pragma unroll 1
        for (int i = 0; i < kk; i += 4) {
            #pragma unroll
            for (int u = 0; u < 4; u++) {
                int   cc = __shfl_sync(hmask, e.x, i + u, 16);
                float ww = __int_as_float(__shfl_sync(hmask, e.y, i + u, 16));
                uint4 hv = tb[(size_t)cc * (D_FEAT / 8) + sl];
                half2* hp = reinterpret_cast<half2*>(&hv);
                #pragma unroll
                for (int q = 0; q < 4; q++) {
                    float2 f = __half22float2(hp[q]);
                    acc[2*q]   = fmaf(ww, f.x, acc[2*q]);
                    acc[2*q+1] = fmaf(ww, f.y, acc[2*q+1]);
                }
            }
        }
    }

    // fused expmap0 + proj: un = max(||u||,1e-15); t = tanh(un);
    //                       f = min(t, MAXNORM) / un
    float ss = 0.f;
    #pragma unroll
    for (int k = 0; k < 8; k++) ss = fmaf(acc[k], acc[k], ss);
    #pragma unroll
    for (int o = 8; o; o >>= 1) ss += __shfl_xor_sync(hmask, ss, o, 16);

    float n  = sqrtf(ss);
    float un = fmaxf(n, 1e-15f);
    float t  = tanhf(un);
    float f  = (t > MAXNORM ? MAXNORM : t) / un;

    float4 o0 = make_float4(acc[0]*f, acc[1]*f, acc[2]*f, acc[3]*f);
    float4 o1 = make_float4(acc[4]*f, acc[5]*f, acc[6]*f, acc[7]*f);
    float4* ob = reinterpret_cast<float4*>(out) + (size_t)row * (D_FEAT / 4);
    ob[sl * 2]     = o0;
    ob[sl * 2 + 1] = o1;
}

// ---------------------------------------------------------------------------
// Launch
// ---------------------------------------------------------------------------
extern "C" void kernel_launch(void* const* d_in, const int* in_sizes, int n_in,
                              void* d_out, int out_size) {
    const float* x    = (const float*)d_in[0];
    const int*   erow = (const int*)d_in[1];
    const int*   ecol = (const int*)d_in[2];
    const float* ew   = (const float*)d_in[3];
    float*       out  = (float*)d_out;

    int n_nodes = in_sizes[0] / D_FEAT;
    int n_edges = in_sizes[3];

    const int T = 256;
    int blocksA = (n_nodes * 32 + T - 1) / T;   // scale: warp per node
    int blocksB = (n_edges + T - 1) / T;        // fill: thread per edge
    int blocksG = (n_nodes * 16 + T - 1) / T;   // gather: half-warp per node

    prep_kernel<<<blocksA + blocksB, T>>>(x, erow, ecol, ew, n_nodes, n_edges, blocksA);
    gather_kernel<<<blocksG, T>>>(out, n_nodes);
}